// round 14
// baseline (speedup 1.0000x reference)
#include <cuda_runtime.h>
#include <cuda_fp16.h>
#include <cstdint>
#include <math.h>

#define HID    4096
#define NHEADS 32
#define HDIM   128
#define BATCH  2
#define SEQ    1024
#define TOKENS 2048
#define H3     12288

// ================= scratch (device globals) =================
__device__ __align__(16) __half g_a[(size_t)TOKENS * HID];
__device__ __align__(16) __half g_wq[(size_t)H3 * HID];     // qkv_w^T [N,K]
__device__ __align__(16) __half g_wo[(size_t)HID * HID];    // attn_ow^T [N,K]
__device__ __align__(16) __half g_qkv[(size_t)TOKENS * H3];
__device__ __align__(16) __half g_vT[(size_t)BATCH * NHEADS * HDIM * SEQ];
__device__ __align__(16) __half g_scores[(size_t)BATCH * NHEADS * SEQ * SEQ]; // e*2^-5 (fp16)
__device__ __align__(16) float g_part[(size_t)BATCH * NHEADS * 8 * SEQ];      // per-tile row sums
__device__ __align__(16) float g_stat[(size_t)BATCH * NHEADS * SEQ];          // 1/rowsum (scaled)
__device__ __align__(16) __half g_ctx[(size_t)TOKENS * HID];

// ================= helpers =================
__device__ __forceinline__ uint32_t smem_u32(const void* p) {
    uint32_t a;
    asm("{ .reg .u64 t; cvta.to.shared.u64 t, %1; cvt.u32.u64 %0, t; }" : "=r"(a) : "l"(p));
    return a;
}
#define CP16(saddr, gptr) \
    asm volatile("cp.async.cg.shared.global [%0], [%1], 16;" :: "r"(saddr), "l"(gptr) : "memory")
#define CP_COMMIT() asm volatile("cp.async.commit_group;" ::: "memory")
#define CP_WAIT1()  asm volatile("cp.async.wait_group 1;" ::: "memory")
#define LDSM4(r0, r1, r2, r3, addr) \
    asm volatile("ldmatrix.sync.aligned.m8n8.x4.shared.b16 {%0,%1,%2,%3}, [%4];" \
        : "=r"(r0), "=r"(r1), "=r"(r2), "=r"(r3) : "r"(addr))
#define MMAF16(c, a, b0v, b1v) \
    asm volatile("mma.sync.aligned.m16n8k16.row.col.f32.f16.f16.f32 " \
        "{%0,%1,%2,%3}, {%4,%5,%6,%7}, {%8,%9}, {%0,%1,%2,%3};" \
        : "+f"((c)[0]), "+f"((c)[1]), "+f"((c)[2]), "+f"((c)[3]) \
        : "r"((a)[0]), "r"((a)[1]), "r"((a)[2]), "r"((a)[3]), "r"(b0v), "r"(b1v))

// ================= FP16 GEMM engine v2: 128 threads, 4 warps (2m x 2n), warp 64x64 =======
// C[M,N] = alpha * A[M,K] @ W[N,K]^T (+bias), A/W fp16 K-major.
// SMEM: 128B rows = 64 halves (one 64-K chunk), SW128 swizzle.  3-stage, one sync/iter.
// MODE 0: plain GEMM (HALF_OUT selects fp16 or fp32 C).
// MODE 1 (QK): causal tile skip; epilogue e = exp(alpha*acc + mask[col]) * 2^-5 (causal 0),
//              fp16-rounded; writes e + deterministic per-(row,bn-tile) sums of rounded e.
// MODE 2 (PV): K limited to (bm+1)*128; epilogue scales fp32 accumulator by stat[row].
#define GM_STAGE 32768
#define GM_BOFF  16384
#define GM_XTRA  (3 * GM_STAGE)
#define GM_SMEM  (3 * GM_STAGE + 2048)   // 100352; 2 CTAs/SM

template<int MODE, bool HAS_BIAS, bool HALF_OUT>
__global__ __launch_bounds__(128, 2) void gemm_f16(
    const __half* __restrict__ A, const __half* __restrict__ W,
    const float* __restrict__ bias,
    float* __restrict__ Cf, __half* __restrict__ Ch,
    const float* __restrict__ stat, const float* __restrict__ mask,
    float* __restrict__ part,
    int K, int lda, int ldb, int ldc,
    long long sA1, long long sA2, long long sB1, long long sB2,
    long long sC1, long long sC2, float alpha)
{
    extern __shared__ char smem[];
    const int bm = blockIdx.x, bn = blockIdx.y;
    if (MODE == 1 && bn > bm) return;

    const uint32_t sbase = smem_u32(smem);
    const int tid = threadIdx.x;
    const int wid = tid >> 5, lane = tid & 31;
    const int warp_m = wid >> 1, warp_n = wid & 1;

    const int z = blockIdx.z;
    const long long offA = (long long)(z >> 5) * sA1 + (long long)(z & 31) * sA2;
    const long long offB = (long long)(z >> 5) * sB1 + (long long)(z & 31) * sB2;
    const long long offC = (long long)(z >> 5) * sC1 + (long long)(z & 31) * sC2;

    const __half* baseA = A + offA + (size_t)bm * 128 * lda;
    const __half* baseB = W + offB + (size_t)bn * 128 * ldb;

    // MODE 2: row scale factors into smem (written before first sync, read after loop)
    float* sstat = (float*)(smem + GM_XTRA);
    if (MODE == 2)
        sstat[tid] = stat[(size_t)z * SEQ + bm * 128 + tid];
    const float* maskz = (MODE == 1) ? (mask + (size_t)(z >> 5) * SEQ) : nullptr;

    // loader: 128 threads; thread -> (row_base r, 16B unit u). unit u covers halves 8u..8u+7.
    const int r_base = tid >> 3;       // 0..15
    const int u = tid & 7;
    const int koff_u = u * 8;
    const uint32_t sw_u = (uint32_t)u * 16u;

#define LOAD_STAGE(st, k0elem) do { \
        const uint32_t _sb = sbase + (uint32_t)(st) * GM_STAGE; \
        _Pragma("unroll") \
        for (int _p = 0; _p < 8; _p++) { \
            const int _r = _p * 16 + r_base; \
            const uint32_t _sw = sw_u ^ (uint32_t)((_r & 7) << 4); \
            CP16(_sb + (uint32_t)_r * 128u + _sw, \
                 baseA + (size_t)_r * lda + (k0elem) + koff_u); \
            CP16(_sb + GM_BOFF + (uint32_t)_r * 128u + _sw, \
                 baseB + (size_t)_r * ldb + (k0elem) + koff_u); \
        } \
    } while (0)

    // ldmatrix lane addressing (16 rows x 16 b16 cols per x4 = one k16 step)
    const int lr = lane & 15;
    const uint32_t kb_lane = (uint32_t)(lane >> 4) * 16u;
    uint32_t a_ro[4], a_xm[4];
#pragma unroll
    for (int mb = 0; mb < 4; mb++) {
        const int r = warp_m * 64 + mb * 16 + lr;
        a_ro[mb] = (uint32_t)r * 128u;
        a_xm[mb] = (uint32_t)((r & 7) << 4);
    }
    uint32_t b_ro[4], b_xm[4];
#pragma unroll
    for (int g = 0; g < 4; g++) {
        const int r = warp_n * 64 + g * 16 + lr;
        b_ro[g] = (uint32_t)r * 128u;
        b_xm[g] = (uint32_t)((r & 7) << 4);
    }

    float acc[4][8][4] = {};

    int Keff = K;
    if (MODE == 2) { int kl = (bm + 1) * 128; Keff = kl < K ? kl : K; }
    const int NC = Keff / 64;

    LOAD_STAGE(0, 0);  CP_COMMIT();
    LOAD_STAGE(1, 64); CP_COMMIT();

    for (int i = 0; i < NC; i++) {
        CP_WAIT1();
        __syncthreads();

        const uint32_t sb = sbase + (uint32_t)(i % 3) * GM_STAGE;
#pragma unroll
        for (int ks = 0; ks < 4; ks++) {           // 4 x k16 per 64-K chunk
            const uint32_t kb = (uint32_t)ks * 32u + kb_lane;
            uint32_t af[4][4];
#pragma unroll
            for (int mb = 0; mb < 4; mb++) {
                LDSM4(af[mb][0], af[mb][1], af[mb][2], af[mb][3],
                      sb + a_ro[mb] + (kb ^ a_xm[mb]));
            }
            uint32_t bf[4][4];
#pragma unroll
            for (int g = 0; g < 4; g++) {
                LDSM4(bf[g][0], bf[g][1], bf[g][2], bf[g][3],
                      sb + GM_BOFF + b_ro[g] + (kb ^ b_xm[g]));
            }
#pragma unroll
            for (int mb = 0; mb < 4; mb++) {
#pragma unroll
                for (int nf = 0; nf < 8; nf++) {
                    const int g = nf >> 1, j = nf & 1;
                    MMAF16(acc[mb][nf], af[mb], bf[g][j], bf[g][2 + j]);
                }
            }
        }

        if (i + 2 < NC) LOAD_STAGE((i + 2) % 3, (size_t)(i + 2) * 64);
        CP_COMMIT();
    }

    // ================= epilogue =================
    const int qrow = lane >> 2;
    const int qcol = (lane & 3) * 2;

    if (MODE == 1) {
        // e = exp(alpha*acc + mask[col]) * 2^-5, causal zeroing, fp16-rounded;
        // deterministic partial row sums over the ROUNDED values.
        float* spart = (float*)(smem + GM_XTRA);   // [2][128]
        float rs[4][2];
#pragma unroll
        for (int mb = 0; mb < 4; mb++) { rs[mb][0] = 0.f; rs[mb][1] = 0.f; }
#pragma unroll
        for (int mb = 0; mb < 4; mb++) {
            const int m0 = bm * 128 + warp_m * 64 + mb * 16 + qrow;
#pragma unroll
            for (int nf = 0; nf < 8; nf++) {
                const int n0 = bn * 128 + warp_n * 64 + nf * 8 + qcol;
                const float mk0 = __ldg(maskz + n0);
                const float mk1 = __ldg(maskz + n0 + 1);
                const float e00 = (n0     <= m0    ) ? __expf(acc[mb][nf][0] * alpha + mk0) * 0.03125f : 0.f;
                const float e01 = (n0 + 1 <= m0    ) ? __expf(acc[mb][nf][1] * alpha + mk1) * 0.03125f : 0.f;
                const float e10 = (n0     <= m0 + 8) ? __expf(acc[mb][nf][2] * alpha + mk0) * 0.03125f : 0.f;
                const float e11 = (n0 + 1 <= m0 + 8) ? __expf(acc[mb][nf][3] * alpha + mk1) * 0.03125f : 0.f;
                const __half h00 = __float2half(e00), h01 = __float2half(e01);
                const __half h10 = __float2half(e10), h11 = __float2half(e11);
                rs[mb][0] += __half2float(h00) + __half2float(h01);
                rs[mb][1] += __half2float(h10) + __half2float(h11);
                __half2 r0, r1;
                r0.x = h00; r0.y = h01;
                r1.x = h10; r1.y = h11;
                *(__half2*)(Ch + offC + (size_t)m0 * ldc + n0)       = r0;
                *(__half2*)(Ch + offC + (size_t)(m0 + 8) * ldc + n0) = r1;
            }
        }
#pragma unroll
        for (int mb = 0; mb < 4; mb++) {
#pragma unroll
            for (int h = 0; h < 2; h++) {
                float v = rs[mb][h];
                v += __shfl_xor_sync(0xffffffffu, v, 1);
                v += __shfl_xor_sync(0xffffffffu, v, 2);
                if ((lane & 3) == 0)
                    spart[warp_n * 128 + warp_m * 64 + mb * 16 + qrow + h * 8] = v;
            }
        }
        __syncthreads();
        {
            const float t = spart[tid] + spart[128 + tid];
            part[(((size_t)z * 8 + bn) << 10) + bm * 128 + tid] = t;
        }
        return;
    }

    // MODE 0 / MODE 2 epilogue
#pragma unroll
    for (int mb = 0; mb < 4; mb++) {
        const int rl0 = warp_m * 64 + mb * 16 + qrow;
        const int m0 = bm * 128 + rl0;
        float il0 = 1.f, il1 = 1.f;
        if (MODE == 2) { il0 = sstat[rl0]; il1 = sstat[rl0 + 8]; }
#pragma unroll
        for (int nf = 0; nf < 8; nf++) {
            const int n0 = bn * 128 + warp_n * 64 + nf * 8 + qcol;
            float b0 = 0.f, b1 = 0.f;
            if (HAS_BIAS) { b0 = bias[n0]; b1 = bias[n0 + 1]; }
            float v00 = acc[mb][nf][0] * alpha + b0;
            float v01 = acc[mb][nf][1] * alpha + b1;
            float v10 = acc[mb][nf][2] * alpha + b0;
            float v11 = acc[mb][nf][3] * alpha + b1;
            if (MODE == 2) { v00 *= il0; v01 *= il0; v10 *= il1; v11 *= il1; }
            if (HALF_OUT) {
                __half2 r0, r1;
                r0.x = __float2half(v00); r0.y = __float2half(v01);
                r1.x = __float2half(v10); r1.y = __float2half(v11);
                *(__half2*)(Ch + offC + (size_t)m0 * ldc + n0)       = r0;
                *(__half2*)(Ch + offC + (size_t)(m0 + 8) * ldc + n0) = r1;
            } else {
                float2 r0, r1;
                r0.x = v00; r0.y = v01;
                r1.x = v10; r1.y = v11;
                *(float2*)(Cf + offC + (size_t)m0 * ldc + n0)       = r0;
                *(float2*)(Cf + offC + (size_t)(m0 + 8) * ldc + n0) = r1;
            }
        }
    }
#undef LOAD_STAGE
}

// ================= recip: il[row] = 1 / sum over kept bn tiles =================
__global__ __launch_bounds__(256) void recip_kernel(
    const float* __restrict__ part, float* __restrict__ stat)
{
    const int idx = blockIdx.x * 256 + threadIdx.x;   // z*1024 + row
    const int z = idx >> 10;
    const int r = idx & 1023;
    const int kt = r >> 7;
    float s = 0.f;
    for (int bn = 0; bn <= kt; bn++)
        s += part[(((size_t)z * 8 + bn) << 10) + r];
    stat[idx] = 1.f / s;
}

// ================= LayerNorm -> fp16 =================
__global__ __launch_bounds__(256) void ln_kernel(
    const float* __restrict__ x, const float* __restrict__ w,
    const float* __restrict__ bvec, __half* __restrict__ o)
{
    int row = blockIdx.x;
    int tid = threadIdx.x;
    const float* xr = x + (size_t)row * HID;
    float4 v[4];
    float sum = 0.f, ss = 0.f;
#pragma unroll
    for (int i = 0; i < 4; i++) {
        v[i] = *(const float4*)(xr + (i * 256 + tid) * 4);
        sum += v[i].x + v[i].y + v[i].z + v[i].w;
        ss  += v[i].x * v[i].x + v[i].y * v[i].y + v[i].z * v[i].z + v[i].w * v[i].w;
    }
#pragma unroll
    for (int off = 16; off > 0; off >>= 1) {
        sum += __shfl_xor_sync(0xffffffffu, sum, off);
        ss  += __shfl_xor_sync(0xffffffffu, ss,  off);
    }
    __shared__ float r0[8], r1[8];
    __shared__ float s_mu, s_rstd;
    int wid = tid >> 5, lane = tid & 31;
    if (lane == 0) { r0[wid] = sum; r1[wid] = ss; }
    __syncthreads();
    if (tid == 0) {
        float s = 0.f, q = 0.f;
        for (int i = 0; i < 8; i++) { s += r0[i]; q += r1[i]; }
        float mu  = s * (1.f / HID);
        float var = q * (1.f / HID) - mu * mu;
        s_mu = mu; s_rstd = rsqrtf(var + 1e-5f);
    }
    __syncthreads();
    float mu = s_mu, rstd = s_rstd;
#pragma unroll
    for (int i = 0; i < 4; i++) {
        int c = (i * 256 + tid) * 4;
        float4 wv = *(const float4*)(w + c);
        float4 bv = *(const float4*)(bvec + c);
        __half h[4];
        h[0] = __float2half((v[i].x - mu) * rstd * wv.x + bv.x);
        h[1] = __float2half((v[i].y - mu) * rstd * wv.y + bv.y);
        h[2] = __float2half((v[i].z - mu) * rstd * wv.z + bv.z);
        h[3] = __float2half((v[i].w - mu) * rstd * wv.w + bv.w);
        *(uint2*)(o + (size_t)row * HID + c) = *(uint2*)h;
    }
}

// ================= transpose + cvt: in[K,N] f32 -> out[N,K] fp16 =================
__global__ __launch_bounds__(256) void transpose_half_kernel(
    const float* __restrict__ in, __half* __restrict__ o, int Kdim, int Ndim)
{
    __shared__ float tile[32][33];
    int n0 = blockIdx.x * 32, k0 = blockIdx.y * 32;
    int tx = threadIdx.x, ty = threadIdx.y;   // block (32,8)
#pragma unroll
    for (int i = 0; i < 32; i += 8)
        tile[ty + i][tx] = in[(size_t)(k0 + ty + i) * Ndim + n0 + tx];
    __syncthreads();
#pragma unroll
    for (int i = 0; i < 32; i += 8)
        o[(size_t)(n0 + ty + i) * Kdim + k0 + tx] = __float2half(tile[tx][ty + i]);
}

// ================= batched fp16 transpose of V: [S,HD] (stride H3) -> [HD,S] =================
__global__ __launch_bounds__(256) void transpose_v_kernel(
    const __half* __restrict__ qkv, __half* __restrict__ vt)
{
    __shared__ __half tile[32][34];
    int z = blockIdx.z;
    int b = z >> 5, h = z & 31;
    const size_t in_off  = (size_t)b * SEQ * H3 + 2 * HID + (size_t)h * HDIM;
    const size_t out_off = (size_t)z * HDIM * SEQ;
    int k0 = blockIdx.x * 32;   // token dim
    int d0 = blockIdx.y * 32;   // head dim
    int tx = threadIdx.x, ty = threadIdx.y;  // (32, 8)
#pragma unroll
    for (int i = 0; i < 32; i += 8)
        tile[ty + i][tx] = qkv[in_off + (size_t)(k0 + ty + i) * H3 + d0 + tx];
    __syncthreads();
#pragma unroll
    for (int i = 0; i < 32; i += 8)
        vt[out_off + (size_t)(d0 + ty + i) * SEQ + k0 + tx] = tile[tx][ty + i];
}

// ================= launch =================
extern "C" void kernel_launch(void* const* d_in, const int* in_sizes, int n_in,
                              void* d_out, int out_size)
{
    const float* x       = (const float*)d_in[0];
    const float* mask    = (const float*)d_in[1];
    const float* norm_w  = (const float*)d_in[2];
    const float* norm_b  = (const float*)d_in[3];
    const float* qkv_w   = (const float*)d_in[4];
    const float* qkv_b   = (const float*)d_in[5];
    const float* attn_ow = (const float*)d_in[6];
    float* out = (float*)d_out;

    __half *p_a, *p_wq, *p_wo, *p_qkv, *p_vt, *p_scores, *p_ctx;
    float *p_part, *p_stat;
    cudaGetSymbolAddress((void**)&p_a,   g_a);
    cudaGetSymbolAddress((void**)&p_wq,  g_wq);
    cudaGetSymbolAddress((void**)&p_wo,  g_wo);
    cudaGetSymbolAddress((void**)&p_qkv, g_qkv);
    cudaGetSymbolAddress((void**)&p_vt,  g_vT);
    cudaGetSymbolAddress((void**)&p_scores, g_scores);
    cudaGetSymbolAddress((void**)&p_part, g_part);
    cudaGetSymbolAddress((void**)&p_stat, g_stat);
    cudaGetSymbolAddress((void**)&p_ctx, g_ctx);

    cudaFuncSetAttribute((const void*)gemm_f16<0, true,  true >, cudaFuncAttributeMaxDynamicSharedMemorySize, GM_SMEM);
    cudaFuncSetAttribute((const void*)gemm_f16<1, false, true >, cudaFuncAttributeMaxDynamicSharedMemorySize, GM_SMEM);
    cudaFuncSetAttribute((const void*)gemm_f16<2, false, true >, cudaFuncAttributeMaxDynamicSharedMemorySize, GM_SMEM);
    cudaFuncSetAttribute((const void*)gemm_f16<0, false, false>, cudaFuncAttributeMaxDynamicSharedMemorySize, GM_SMEM);

    const float inv_sqrt_hd = 0.08838834764831845f;  // 1/sqrt(128)

    // 1) LayerNorm -> fp16 activations
    ln_kernel<<<TOKENS, 256>>>(x, norm_w, norm_b, p_a);

    // 2) weight transpose+cvt to [N,K] fp16
    transpose_half_kernel<<<dim3(H3 / 32, HID / 32), dim3(32, 8)>>>(qkv_w, p_wq, HID, H3);
    transpose_half_kernel<<<dim3(HID / 32, HID / 32), dim3(32, 8)>>>(attn_ow, p_wo, HID, HID);

    // 3) QKV GEMM + bias -> fp16 qkv
    gemm_f16<0, true, true><<<dim3(TOKENS / 128, H3 / 128), 128, GM_SMEM>>>(
        p_a, p_wq, qkv_b, nullptr, p_qkv, nullptr, nullptr, nullptr,
        HID, HID, HID, H3,
        0, 0, 0, 0, 0, 0, 1.0f);

    // 4) transpose V -> vT [z][HD][S]
    transpose_v_kernel<<<dim3(SEQ / 32, HDIM / 32, BATCH * NHEADS), dim3(32, 8)>>>(p_qkv, p_vt);

    // 5) QK^T with fused softmax-numerator epilogue: writes e = exp(s+mask)*2^-5 (fp16)
    //    + deterministic per-tile row sums of the rounded values
    gemm_f16<1, false, true><<<dim3(SEQ / 128, SEQ / 128, BATCH * NHEADS), 128, GM_SMEM>>>(
        p_qkv, p_qkv + HID, nullptr, nullptr, p_scores, nullptr, mask, p_part,
        HDIM, H3, H3, SEQ,
        (long long)SEQ * H3, HDIM,
        (long long)SEQ * H3, HDIM,
        (long long)NHEADS * SEQ * SEQ, (long long)SEQ * SEQ,
        inv_sqrt_hd);

    // 6) il = 1/rowsum (scale cancels exactly)
    recip_kernel<<<(BATCH * NHEADS * SEQ) / 256, 256>>>(p_part, p_stat);

    // 7) ctx = il * (e @ V); il applied to fp32 accumulator in epilogue; fp16 out [b,s,h*hd]
    gemm_f16<2, false, true><<<dim3(SEQ / 128, HDIM / 128, BATCH * NHEADS), 128, GM_SMEM>>>(
        p_scores, p_vt, nullptr, nullptr, p_ctx, p_stat, nullptr, nullptr,
        SEQ, SEQ, SEQ, HID,
        (long long)NHEADS * SEQ * SEQ, (long long)SEQ * SEQ,
        (long long)NHEADS * HDIM * SEQ, (long long)HDIM * SEQ,
        (long long)SEQ * HID, HDIM,
        1.0f);

    // 8) out = ctx @ attn_ow, fp32 out
    gemm_f16<0, false, false><<<dim3(TOKENS / 128, HID / 128), 128, GM_SMEM>>>(
        p_ctx, p_wo, nullptr, out, nullptr, nullptr, nullptr, nullptr,
        HID, HID, HID, HID,
        0, 0, 0, 0, 0, 0, 1.0f);
}

// round 16
// speedup vs baseline: 1.0515x; 1.0515x over previous
#include <cuda_runtime.h>
#include <cuda_fp16.h>
#include <cstdint>
#include <math.h>

#define HID    4096
#define NHEADS 32
#define HDIM   128
#define BATCH  2
#define SEQ    1024
#define TOKENS 2048
#define H3     12288

// ================= scratch (device globals) =================
__device__ __align__(16) __half g_a[(size_t)TOKENS * HID];
__device__ __align__(16) __half g_wq[(size_t)H3 * HID];     // qkv_w^T [N,K]
__device__ __align__(16) __half g_wo[(size_t)HID * HID];    // attn_ow^T [N,K]
__device__ __align__(16) __half g_qkv[(size_t)TOKENS * H3]; // only Q,K regions used
__device__ __align__(16) __half g_vT[(size_t)BATCH * NHEADS * HDIM * SEQ];
__device__ __align__(16) __half g_scores[(size_t)BATCH * NHEADS * SEQ * SEQ]; // e*2^-5 (fp16)
__device__ __align__(16) float g_part[(size_t)BATCH * NHEADS * 8 * SEQ];      // per-tile row sums
__device__ __align__(16) float g_stat[(size_t)BATCH * NHEADS * SEQ];          // 1/rowsum (scaled)
__device__ __align__(16) __half g_ctx[(size_t)TOKENS * HID];

// ================= helpers =================
__device__ __forceinline__ uint32_t smem_u32(const void* p) {
    uint32_t a;
    asm("{ .reg .u64 t; cvta.to.shared.u64 t, %1; cvt.u32.u64 %0, t; }" : "=r"(a) : "l"(p));
    return a;
}
#define CP16(saddr, gptr) \
    asm volatile("cp.async.cg.shared.global [%0], [%1], 16;" :: "r"(saddr), "l"(gptr) : "memory")
#define CP_COMMIT() asm volatile("cp.async.commit_group;" ::: "memory")
#define CP_WAIT1()  asm volatile("cp.async.wait_group 1;" ::: "memory")
#define LDSM4(r0, r1, r2, r3, addr) \
    asm volatile("ldmatrix.sync.aligned.m8n8.x4.shared.b16 {%0,%1,%2,%3}, [%4];" \
        : "=r"(r0), "=r"(r1), "=r"(r2), "=r"(r3) : "r"(addr))
#define MMAF16(c, a, b0v, b1v) \
    asm volatile("mma.sync.aligned.m16n8k16.row.col.f32.f16.f16.f32 " \
        "{%0,%1,%2,%3}, {%4,%5,%6,%7}, {%8,%9}, {%0,%1,%2,%3};" \
        : "+f"((c)[0]), "+f"((c)[1]), "+f"((c)[2]), "+f"((c)[3]) \
        : "r"((a)[0]), "r"((a)[1]), "r"((a)[2]), "r"((a)[3]), "r"(b0v), "r"(b1v))

// ================= FP16 GEMM engine (R13 config: 256 thr, 8 warps 2m x 4n, warp 64x32) ====
// C[M,N] = alpha * A[M,K] @ W[N,K]^T (+bias), A/W fp16 K-major.
// SMEM: 128B rows = 64 halves (one 64-K chunk), SW128 swizzle. 3-stage, one sync/iter.
// MODE 0: plain GEMM (HALF_OUT selects fp16 or fp32 C).
//         VSPLIT: QKV mode — tiles with bn>=64 (V region) are written directly into
//         vT [z][HD][S] layout (transpose fused into epilogue); Q/K tiles go to Ch.
// MODE 1 (QK): causal tile skip; epilogue e = exp(alpha*acc + mask[col]) * 2^-5 (causal 0),
//              fp16-rounded; writes e + deterministic per-(row,bn-tile) sums of rounded e.
// MODE 2 (PV): K limited to (bm+1)*128; epilogue scales fp32 accumulator by stat[row].
#define GM_STAGE 32768
#define GM_BOFF  16384
#define GM_XTRA  (3 * GM_STAGE)
#define GM_SMEM  (3 * GM_STAGE + 2048)   // 100352; 2 CTAs/SM

template<int MODE, bool HAS_BIAS, bool HALF_OUT, bool VSPLIT>
__global__ __launch_bounds__(256, 2) void gemm_f16(
    const __half* __restrict__ A, const __half* __restrict__ W,
    const float* __restrict__ bias,
    float* __restrict__ Cf, __half* __restrict__ Ch,
    __half* __restrict__ Vt,
    const float* __restrict__ stat, const float* __restrict__ mask,
    float* __restrict__ part,
    int K, int lda, int ldb, int ldc,
    long long sA1, long long sA2, long long sB1, long long sB2,
    long long sC1, long long sC2, float alpha)
{
    extern __shared__ char smem[];
    const int bm = blockIdx.x, bn = blockIdx.y;
    if (MODE == 1 && bn > bm) return;

    const uint32_t sbase = smem_u32(smem);
    const int tid = threadIdx.x;
    const int wid = tid >> 5, lane = tid & 31;
    const int warp_m = wid >> 2, warp_n = wid & 3;

    const int z = blockIdx.z;
    const long long offA = (long long)(z >> 5) * sA1 + (long long)(z & 31) * sA2;
    const long long offB = (long long)(z >> 5) * sB1 + (long long)(z & 31) * sB2;
    const long long offC = (long long)(z >> 5) * sC1 + (long long)(z & 31) * sC2;

    const __half* baseA = A + offA + (size_t)bm * 128 * lda;
    const __half* baseB = W + offB + (size_t)bn * 128 * ldb;

    // MODE 2: row scale factors into smem (written before first sync, read after loop)
    float* sstat = (float*)(smem + GM_XTRA);
    if (MODE == 2) {
        if (tid < 128)
            sstat[tid] = stat[(size_t)z * SEQ + bm * 128 + tid];
    }
    const float* maskz = (MODE == 1) ? (mask + (size_t)(z >> 5) * SEQ) : nullptr;

    // loader: thread -> (row_base r, 16B unit u). unit u covers halves 8u..8u+7.
    const int r_base = tid >> 3;
    const int u = tid & 7;
    const int koff_u = u * 8;
    const uint32_t sw_u = (uint32_t)u * 16u;

#define LOAD_STAGE(st, k0elem) do { \
        const uint32_t _sb = sbase + (uint32_t)(st) * GM_STAGE; \
        _Pragma("unroll") \
        for (int _p = 0; _p < 4; _p++) { \
            const int _r = _p * 32 + r_base; \
            const uint32_t _sw = sw_u ^ (uint32_t)((_r & 7) << 4); \
            CP16(_sb + (uint32_t)_r * 128u + _sw, \
                 baseA + (size_t)_r * lda + (k0elem) + koff_u); \
            CP16(_sb + GM_BOFF + (uint32_t)_r * 128u + _sw, \
                 baseB + (size_t)_r * ldb + (k0elem) + koff_u); \
        } \
    } while (0)

    // ldmatrix lane addressing (16 rows x 16 b16 cols per x4 = one k16 step)
    const int lr = lane & 15;
    const uint32_t kb_lane = (uint32_t)(lane >> 4) * 16u;
    uint32_t a_ro[4], a_xm[4];
#pragma unroll
    for (int mb = 0; mb < 4; mb++) {
        const int r = warp_m * 64 + mb * 16 + lr;
        a_ro[mb] = (uint32_t)r * 128u;
        a_xm[mb] = (uint32_t)((r & 7) << 4);
    }
    uint32_t b_ro[2], b_xm[2];
#pragma unroll
    for (int g = 0; g < 2; g++) {
        const int r = warp_n * 32 + g * 16 + lr;
        b_ro[g] = (uint32_t)r * 128u;
        b_xm[g] = (uint32_t)((r & 7) << 4);
    }

    float acc[4][4][4] = {};

    int Keff = K;
    if (MODE == 2) { int kl = (bm + 1) * 128; Keff = kl < K ? kl : K; }
    const int NC = Keff / 64;

    LOAD_STAGE(0, 0);  CP_COMMIT();
    LOAD_STAGE(1, 64); CP_COMMIT();

    for (int i = 0; i < NC; i++) {
        CP_WAIT1();
        __syncthreads();

        const uint32_t sb = sbase + (uint32_t)(i % 3) * GM_STAGE;
#pragma unroll
        for (int ks = 0; ks < 4; ks++) {           // 4 x k16 per 64-K chunk
            const uint32_t kb = (uint32_t)ks * 32u + kb_lane;
            uint32_t af[4][4];
#pragma unroll
            for (int mb = 0; mb < 4; mb++) {
                LDSM4(af[mb][0], af[mb][1], af[mb][2], af[mb][3],
                      sb + a_ro[mb] + (kb ^ a_xm[mb]));
            }
            uint32_t bf[2][4];
#pragma unroll
            for (int g = 0; g < 2; g++) {
                LDSM4(bf[g][0], bf[g][1], bf[g][2], bf[g][3],
                      sb + GM_BOFF + b_ro[g] + (kb ^ b_xm[g]));
            }
#pragma unroll
            for (int mb = 0; mb < 4; mb++) {
#pragma unroll
                for (int nf = 0; nf < 4; nf++) {
                    const int g = nf >> 1, j = nf & 1;
                    MMAF16(acc[mb][nf], af[mb], bf[g][j], bf[g][2 + j]);
                }
            }
        }

        if (i + 2 < NC) LOAD_STAGE((i + 2) % 3, (size_t)(i + 2) * 64);
        CP_COMMIT();
    }

    // ================= epilogue =================
    const int qrow = lane >> 2;
    const int qcol = (lane & 3) * 2;

    if (MODE == 1) {
        // e = exp(alpha*acc + mask[col]) * 2^-5, causal zeroing, fp16-rounded;
        // deterministic partial row sums over the ROUNDED values.
        float* spart = (float*)(smem + GM_XTRA);   // [4][128]
        float rs[4][2];
#pragma unroll
        for (int mb = 0; mb < 4; mb++) { rs[mb][0] = 0.f; rs[mb][1] = 0.f; }
#pragma unroll
        for (int mb = 0; mb < 4; mb++) {
            const int m0 = bm * 128 + warp_m * 64 + mb * 16 + qrow;
#pragma unroll
            for (int nf = 0; nf < 4; nf++) {
                const int n0 = bn * 128 + warp_n * 32 + nf * 8 + qcol;
                const float mk0 = __ldg(maskz + n0);
                const float mk1 = __ldg(maskz + n0 + 1);
                const float e00 = (n0     <= m0    ) ? __expf(acc[mb][nf][0] * alpha + mk0) * 0.03125f : 0.f;
                const float e01 = (n0 + 1 <= m0    ) ? __expf(acc[mb][nf][1] * alpha + mk1) * 0.03125f : 0.f;
                const float e10 = (n0     <= m0 + 8) ? __expf(acc[mb][nf][2] * alpha + mk0) * 0.03125f : 0.f;
                const float e11 = (n0 + 1 <= m0 + 8) ? __expf(acc[mb][nf][3] * alpha + mk1) * 0.03125f : 0.f;
                const __half h00 = __float2half(e00), h01 = __float2half(e01);
                const __half h10 = __float2half(e10), h11 = __float2half(e11);
                rs[mb][0] += __half2float(h00) + __half2float(h01);
                rs[mb][1] += __half2float(h10) + __half2float(h11);
                __half2 r0, r1;
                r0.x = h00; r0.y = h01;
                r1.x = h10; r1.y = h11;
                *(__half2*)(Ch + offC + (size_t)m0 * ldc + n0)       = r0;
                *(__half2*)(Ch + offC + (size_t)(m0 + 8) * ldc + n0) = r1;
            }
        }
#pragma unroll
        for (int mb = 0; mb < 4; mb++) {
#pragma unroll
            for (int h = 0; h < 2; h++) {
                float v = rs[mb][h];
                v += __shfl_xor_sync(0xffffffffu, v, 1);
                v += __shfl_xor_sync(0xffffffffu, v, 2);
                if ((lane & 3) == 0)
                    spart[warp_n * 128 + warp_m * 64 + mb * 16 + qrow + h * 8] = v;
            }
        }
        __syncthreads();
        if (tid < 128) {
            const float t = spart[tid] + spart[128 + tid] + spart[256 + tid] + spart[384 + tid];
            part[(((size_t)z * 8 + bn) << 10) + bm * 128 + tid] = t;
        }
        return;
    }

    // MODE 0 / MODE 2 epilogue
    const bool vtile = VSPLIT && (bn >= 64);   // V region of the QKV output
#pragma unroll
    for (int mb = 0; mb < 4; mb++) {
        const int rl0 = warp_m * 64 + mb * 16 + qrow;
        const int m0 = bm * 128 + rl0;
        float il0 = 1.f, il1 = 1.f;
        if (MODE == 2) { il0 = sstat[rl0]; il1 = sstat[rl0 + 8]; }
#pragma unroll
        for (int nf = 0; nf < 4; nf++) {
            const int n0 = bn * 128 + warp_n * 32 + nf * 8 + qcol;
            float b0 = 0.f, b1 = 0.f;
            if (HAS_BIAS) { b0 = bias[n0]; b1 = bias[n0 + 1]; }
            float v00 = acc[mb][nf][0] * alpha + b0;
            float v01 = acc[mb][nf][1] * alpha + b1;
            float v10 = acc[mb][nf][2] * alpha + b0;
            float v11 = acc[mb][nf][3] * alpha + b1;
            if (MODE == 2) { v00 *= il0; v01 *= il0; v10 *= il1; v11 *= il1; }
            if (vtile) {
                // fused V transpose: n0 in [8192,12288) -> head h, dim d; token m0 -> (b,s)
                const int hh = (n0 - 2 * HID) >> 7;
                const int d  = n0 & 127;
                const int bb = m0 >> 10;
                const int s  = m0 & 1023;
                __half* vbase = Vt + ((size_t)(bb * NHEADS + hh) * HDIM) * SEQ;
                vbase[(size_t)d * SEQ + s]             = __float2half(v00);
                vbase[(size_t)(d + 1) * SEQ + s]       = __float2half(v01);
                vbase[(size_t)d * SEQ + s + 8]         = __float2half(v10);
                vbase[(size_t)(d + 1) * SEQ + s + 8]   = __float2half(v11);
            } else if (HALF_OUT) {
                __half2 r0, r1;
                r0.x = __float2half(v00); r0.y = __float2half(v01);
                r1.x = __float2half(v10); r1.y = __float2half(v11);
                *(__half2*)(Ch + offC + (size_t)m0 * ldc + n0)       = r0;
                *(__half2*)(Ch + offC + (size_t)(m0 + 8) * ldc + n0) = r1;
            } else {
                float2 r0, r1;
                r0.x = v00; r0.y = v01;
                r1.x = v10; r1.y = v11;
                *(float2*)(Cf + offC + (size_t)m0 * ldc + n0)       = r0;
                *(float2*)(Cf + offC + (size_t)(m0 + 8) * ldc + n0) = r1;
            }
        }
    }
#undef LOAD_STAGE
}

// ================= recip: il[row] = 1 / sum over kept bn tiles =================
__global__ __launch_bounds__(256) void recip_kernel(
    const float* __restrict__ part, float* __restrict__ stat)
{
    const int idx = blockIdx.x * 256 + threadIdx.x;   // z*1024 + row
    const int z = idx >> 10;
    const int r = idx & 1023;
    const int kt = r >> 7;
    float s = 0.f;
    for (int bn = 0; bn <= kt; bn++)
        s += part[(((size_t)z * 8 + bn) << 10) + r];
    stat[idx] = 1.f / s;
}

// ================= LayerNorm -> fp16 =================
__global__ __launch_bounds__(256) void ln_kernel(
    const float* __restrict__ x, const float* __restrict__ w,
    const float* __restrict__ bvec, __half* __restrict__ o)
{
    int row = blockIdx.x;
    int tid = threadIdx.x;
    const float* xr = x + (size_t)row * HID;
    float4 v[4];
    float sum = 0.f, ss = 0.f;
#pragma unroll
    for (int i = 0; i < 4; i++) {
        v[i] = *(const float4*)(xr + (i * 256 + tid) * 4);
        sum += v[i].x + v[i].y + v[i].z + v[i].w;
        ss  += v[i].x * v[i].x + v[i].y * v[i].y + v[i].z * v[i].z + v[i].w * v[i].w;
    }
#pragma unroll
    for (int off = 16; off > 0; off >>= 1) {
        sum += __shfl_xor_sync(0xffffffffu, sum, off);
        ss  += __shfl_xor_sync(0xffffffffu, ss,  off);
    }
    __shared__ float r0[8], r1[8];
    __shared__ float s_mu, s_rstd;
    int wid = tid >> 5, lane = tid & 31;
    if (lane == 0) { r0[wid] = sum; r1[wid] = ss; }
    __syncthreads();
    if (tid == 0) {
        float s = 0.f, q = 0.f;
        for (int i = 0; i < 8; i++) { s += r0[i]; q += r1[i]; }
        float mu  = s * (1.f / HID);
        float var = q * (1.f / HID) - mu * mu;
        s_mu = mu; s_rstd = rsqrtf(var + 1e-5f);
    }
    __syncthreads();
    float mu = s_mu, rstd = s_rstd;
#pragma unroll
    for (int i = 0; i < 4; i++) {
        int c = (i * 256 + tid) * 4;
        float4 wv = *(const float4*)(w + c);
        float4 bv = *(const float4*)(bvec + c);
        __half h[4];
        h[0] = __float2half((v[i].x - mu) * rstd * wv.x + bv.x);
        h[1] = __float2half((v[i].y - mu) * rstd * wv.y + bv.y);
        h[2] = __float2half((v[i].z - mu) * rstd * wv.z + bv.z);
        h[3] = __float2half((v[i].w - mu) * rstd * wv.w + bv.w);
        *(uint2*)(o + (size_t)row * HID + c) = *(uint2*)h;
    }
}

// ================= transpose + cvt: in[K,N] f32 -> out[N,K] fp16 =================
__global__ __launch_bounds__(256) void transpose_half_kernel(
    const float* __restrict__ in, __half* __restrict__ o, int Kdim, int Ndim)
{
    __shared__ float tile[32][33];
    int n0 = blockIdx.x * 32, k0 = blockIdx.y * 32;
    int tx = threadIdx.x, ty = threadIdx.y;   // block (32,8)
#pragma unroll
    for (int i = 0; i < 32; i += 8)
        tile[ty + i][tx] = in[(size_t)(k0 + ty + i) * Ndim + n0 + tx];
    __syncthreads();
#pragma unroll
    for (int i = 0; i < 32; i += 8)
        o[(size_t)(n0 + ty + i) * Kdim + k0 + tx] = __float2half(tile[tx][ty + i]);
}

// ================= launch =================
extern "C" void kernel_launch(void* const* d_in, const int* in_sizes, int n_in,
                              void* d_out, int out_size)
{
    const float* x       = (const float*)d_in[0];
    const float* mask    = (const float*)d_in[1];
    const float* norm_w  = (const float*)d_in[2];
    const float* norm_b  = (const float*)d_in[3];
    const float* qkv_w   = (const float*)d_in[4];
    const float* qkv_b   = (const float*)d_in[5];
    const float* attn_ow = (const float*)d_in[6];
    float* out = (float*)d_out;

    __half *p_a, *p_wq, *p_wo, *p_qkv, *p_vt, *p_scores, *p_ctx;
    float *p_part, *p_stat;
    cudaGetSymbolAddress((void**)&p_a,   g_a);
    cudaGetSymbolAddress((void**)&p_wq,  g_wq);
    cudaGetSymbolAddress((void**)&p_wo,  g_wo);
    cudaGetSymbolAddress((void**)&p_qkv, g_qkv);
    cudaGetSymbolAddress((void**)&p_vt,  g_vT);
    cudaGetSymbolAddress((void**)&p_scores, g_scores);
    cudaGetSymbolAddress((void**)&p_part, g_part);
    cudaGetSymbolAddress((void**)&p_stat, g_stat);
    cudaGetSymbolAddress((void**)&p_ctx, g_ctx);

    cudaFuncSetAttribute((const void*)gemm_f16<0, true,  true,  true >, cudaFuncAttributeMaxDynamicSharedMemorySize, GM_SMEM);
    cudaFuncSetAttribute((const void*)gemm_f16<1, false, true,  false>, cudaFuncAttributeMaxDynamicSharedMemorySize, GM_SMEM);
    cudaFuncSetAttribute((const void*)gemm_f16<2, false, true,  false>, cudaFuncAttributeMaxDynamicSharedMemorySize, GM_SMEM);
    cudaFuncSetAttribute((const void*)gemm_f16<0, false, false, false>, cudaFuncAttributeMaxDynamicSharedMemorySize, GM_SMEM);

    const float inv_sqrt_hd = 0.08838834764831845f;  // 1/sqrt(128)

    // 1) LayerNorm -> fp16 activations
    ln_kernel<<<TOKENS, 256>>>(x, norm_w, norm_b, p_a);

    // 2) weight transpose+cvt to [N,K] fp16
    transpose_half_kernel<<<dim3(H3 / 32, HID / 32), dim3(32, 8)>>>(qkv_w, p_wq, HID, H3);
    transpose_half_kernel<<<dim3(HID / 32, HID / 32), dim3(32, 8)>>>(attn_ow, p_wo, HID, HID);

    // 3) QKV GEMM + bias -> Q,K into g_qkv; V written directly transposed into vT
    gemm_f16<0, true, true, true><<<dim3(TOKENS / 128, H3 / 128), 256, GM_SMEM>>>(
        p_a, p_wq, qkv_b, nullptr, p_qkv, p_vt, nullptr, nullptr, nullptr,
        HID, HID, HID, H3,
        0, 0, 0, 0, 0, 0, 1.0f);

    // 4) QK^T with fused softmax-numerator epilogue: writes e = exp(s+mask)*2^-5 (fp16)
    //    + deterministic per-tile row sums of the rounded values
    gemm_f16<1, false, true, false><<<dim3(SEQ / 128, SEQ / 128, BATCH * NHEADS), 256, GM_SMEM>>>(
        p_qkv, p_qkv + HID, nullptr, nullptr, p_scores, nullptr, nullptr, mask, p_part,
        HDIM, H3, H3, SEQ,
        (long long)SEQ * H3, HDIM,
        (long long)SEQ * H3, HDIM,
        (long long)NHEADS * SEQ * SEQ, (long long)SEQ * SEQ,
        inv_sqrt_hd);

    // 5) il = 1/rowsum (scale cancels exactly)
    recip_kernel<<<(BATCH * NHEADS * SEQ) / 256, 256>>>(p_part, p_stat);

    // 6) ctx = il * (e @ V); il applied to fp32 accumulator in epilogue; fp16 out [b,s,h*hd]
    gemm_f16<2, false, true, false><<<dim3(SEQ / 128, HDIM / 128, BATCH * NHEADS), 256, GM_SMEM>>>(
        p_scores, p_vt, nullptr, nullptr, p_ctx, nullptr, p_stat, nullptr, nullptr,
        SEQ, SEQ, SEQ, HID,
        (long long)NHEADS * SEQ * SEQ, (long long)SEQ * SEQ,
        (long long)NHEADS * HDIM * SEQ, (long long)HDIM * SEQ,
        (long long)SEQ * HID, HDIM,
        1.0f);

    // 7) out = ctx @ attn_ow, fp32 out
    gemm_f16<0, false, false, false><<<dim3(TOKENS / 128, HID / 128), 256, GM_SMEM>>>(
        p_ctx, p_wo, nullptr, out, nullptr, nullptr, nullptr, nullptr, nullptr,
        HID, HID, HID, HID,
        0, 0, 0, 0, 0, 0, 1.0f);
}